// round 5
// baseline (speedup 1.0000x reference)
#include <cuda_runtime.h>
#include <math.h>
#include <stdint.h>

// ---------------------------------------------------------------------------
// MSEObserver: 100-candidate symmetric-threshold grid search, Lp loss p=2.4.
// R5: direct 32K-bin hash-permuted histogram (collapse stage removed; the
// hash perm already fixes the slice-hotness that killed direct 32K in R2),
// minimal init (only g_hist), and 2x-unrolled hist inner loop (8 elems/iter,
// front-batched LDG.128 pair for MLP) to close the gap to the REDG lane floor
// (~1.29 cyc/lane/SM). Scoring path structurally identical to R4, centers
// re-derived for direct binning.
// ---------------------------------------------------------------------------

#define NBINS 32768                        // histogram + scoring bins (128 KB)
#define NUM_T 100
#define NCHUNK 8
#define BINS_PER_CHUNK (NBINS / NCHUNK)    // 4096

#define PERM_MULT 0x9E3779B1u              // odd -> bijective mod 2^15
#define PERM_MASK (NBINS - 1)
#define MAGIC 12582912.0f                  // 2^23 + 2^22
#define BIN_OFF 2.0f                       // low-side safety offset
#define BIN_SPAN ((float)(NBINS - 8))      // top-side safety margin

__device__ unsigned int g_absmax_bits;     // max|x| >= 0 -> raw-bit atomicMax ok
__device__ unsigned int g_hist[NBINS];     // permuted layout
__device__ unsigned int g_hist_s[NBINS];   // depermuted (linear) layout
__device__ double       g_partial[NUM_T][NCHUNK];

// ---------------------------------------------------------------------------
// K0: zero g_hist + absmax. (g_hist_s / g_partial are fully overwritten each
// replay by k_deperm / k_scores, so no reset needed -> deterministic.)
// ---------------------------------------------------------------------------
__global__ void k_init() {
    int idx = blockIdx.x * blockDim.x + threadIdx.x;
    if (idx < NBINS) g_hist[idx] = 0u;
    if (idx == 0) g_absmax_bits = 0u;
}

// ---------------------------------------------------------------------------
// K1: absmax = max(|x|). One FMNMX(|.|)/elem; DRAM-roofline pass (~17 us).
// ---------------------------------------------------------------------------
__global__ void __launch_bounds__(256) k_absmax(const float* __restrict__ x, int n) {
    const int n4 = n >> 2;
    const float4* __restrict__ x4 = (const float4*)x;

    float m0 = 0.0f, m1 = 0.0f;
    for (int i = blockIdx.x * blockDim.x + threadIdx.x; i < n4;
         i += gridDim.x * blockDim.x) {
        float4 v = x4[i];
        m0 = fmaxf(m0, fmaxf(fabsf(v.x), fabsf(v.y)));
        m1 = fmaxf(m1, fmaxf(fabsf(v.z), fabsf(v.w)));
    }
    if (blockIdx.x == 0) {                       // tail
        int t = n4 * 4 + threadIdx.x;
        if (t < n) m0 = fmaxf(m0, fabsf(x[t]));
    }
    float m = fmaxf(m0, m1);

    for (int o = 16; o > 0; o >>= 1)
        m = fmaxf(m, __shfl_xor_sync(0xffffffffu, m, o));
    __shared__ float sm[8];
    int wid = threadIdx.x >> 5, lid = threadIdx.x & 31;
    if (lid == 0) sm[wid] = m;
    __syncthreads();
    if (wid == 0) {
        m = (lid < 8) ? sm[lid] : 0.0f;
        for (int o = 4; o > 0; o >>= 1)
            m = fmaxf(m, __shfl_xor_sync(0xffffffffu, m, o));
        if (lid == 0) atomicMax(&g_absmax_bits, __float_as_uint(m));
    }
}

// ---------------------------------------------------------------------------
// K2: hash-permuted 32K-bin histogram over [-xr, xr].
// bin = round((v+xr)*invw) + BIN_OFF via ONE fused FFMA + magic number;
// invw margined so 2 <= bin <= NBINS-6 structurally (no clamps).
// 8 elements per iteration, both LDG.128 issued before any REDG (MLP).
// ---------------------------------------------------------------------------
__global__ void __launch_bounds__(256) k_hist(const float* __restrict__ x, int n) {
    const float xr   = __uint_as_float(g_absmax_bits);
    const float invw = BIN_SPAN / (2.0f * xr);
    const float C    = xr * invw + (MAGIC + BIN_OFF);   // folds shift+off+magic

    const int n4 = n >> 2;
    const int n8 = n4 >> 1;                             // float4 pairs
    const float4* __restrict__ x4 = (const float4*)x;

    const int stride = gridDim.x * blockDim.x;
    for (int i = blockIdx.x * blockDim.x + threadIdx.x; i < n8; i += stride) {
        float4 a = x4[2 * i];                           // front-batched loads
        float4 b = x4[2 * i + 1];
        float vv[8] = {a.x, a.y, a.z, a.w, b.x, b.y, b.z, b.w};
        #pragma unroll
        for (int k = 0; k < 8; k++) {
            float f = fmaf(vv[k], invw, C);             // t + magic (rn)
            unsigned int bi = __float_as_uint(f) & 0x3FFFFFu;
            unsigned int p = (bi * PERM_MULT) & PERM_MASK;
            atomicAdd(&g_hist[p], 1u);
        }
    }
    if (blockIdx.x == 0) {                              // tail (n % 8 != 0)
        for (int t = n8 * 8 + threadIdx.x; t < n; t += blockDim.x) {
            float f = fmaf(x[t], invw, C);
            unsigned int bi = __float_as_uint(f) & 0x3FFFFFu;
            unsigned int p = (bi * PERM_MULT) & PERM_MASK;
            atomicAdd(&g_hist[p], 1u);
        }
    }
}

// ---------------------------------------------------------------------------
// K2b: deperm 32K bins into linear order for the scoring scan (~0.5 us).
// ---------------------------------------------------------------------------
__global__ void __launch_bounds__(256) k_deperm() {
    int b = blockIdx.x * blockDim.x + threadIdx.x;
    if (b < NBINS)
        g_hist_s[b] = g_hist[((unsigned int)b * PERM_MULT) & PERM_MASK];
}

// ---------------------------------------------------------------------------
// K3: grid (NUM_T, NCHUNK). Score candidate i+1 over a chunk of bins.
// Bin h holds values with round((v+xr)*invw)+OFF = h -> center value
// c = (h - OFF)*wH - xr. fp32 inner loop + Kahan; double block reduce;
// deterministic single store per block.
// ---------------------------------------------------------------------------
__global__ void __launch_bounds__(256) k_scores() {
    const int i     = blockIdx.x + 1;
    const int chunk = blockIdx.y;

    const float xr   = __uint_as_float(g_absmax_bits);
    const float invw = BIN_SPAN / (2.0f * xr);
    const float wH   = 1.0f / invw;

    const float thres = xr / 100.0f * (float)i;          // match ref fp32 order
    const float scale = fmaxf(thres / 127.5f, 1e-8f);
    const float inv_scale = 1.0f / scale;

    const float c0 = -BIN_OFF * wH - xr;                 // c = b*wH + c0

    float acc = 0.0f, comp = 0.0f;                        // Kahan
    const int b_end = (chunk + 1) * BINS_PER_CHUNK;
    for (int b = chunk * BINS_PER_CHUNK + threadIdx.x; b < b_end; b += 256) {
        unsigned int cnt = g_hist_s[b];
        if (cnt == 0u) continue;
        float c = fmaf((float)b, wH, c0);                 // bin-center value
        float t = c * inv_scale;
        float r = rintf(t);                               // round half-even
        r = fminf(fmaxf(r, -128.0f), 127.0f);             // clip
        float e = fabsf(fmaf(-r, scale, c));              // |c - r*scale|
        float p = exp2f(2.4f * __log2f(e));               // e^2.4 (e=0 -> 0)
        float term = (float)cnt * p;
        float y = term - comp;
        float s = acc + y;
        comp = (s - acc) - y;
        acc = s;
    }

    __shared__ double sacc[256];
    sacc[threadIdx.x] = (double)acc;
    __syncthreads();
    for (int s = 128; s > 0; s >>= 1) {
        if (threadIdx.x < s) sacc[threadIdx.x] += sacc[threadIdx.x + s];
        __syncthreads();
    }
    if (threadIdx.x == 0) g_partial[blockIdx.x][chunk] = sacc[0];
}

// ---------------------------------------------------------------------------
// K4: fixed-order chunk sums, argmin (strict <, ascending i) -> output.
// ---------------------------------------------------------------------------
__global__ void k_argmin(float* __restrict__ out) {
    if (threadIdx.x == 0 && blockIdx.x == 0) {
        const float xr = __uint_as_float(g_absmax_bits);

        double best = 1e300;
        int bi = 1;
        #pragma unroll 1
        for (int i = 1; i <= NUM_T; i++) {
            double s = 0.0;
            #pragma unroll
            for (int c = 0; c < NCHUNK; c++) s += g_partial[i - 1][c];
            if (s < best) { best = s; bi = i; }
        }
        float thres = xr / 100.0f * (float)bi;
        out[0] = -thres;
        out[1] =  thres;
    }
}

// ---------------------------------------------------------------------------
// Launch: 6 kernels on the default stream (graph-capturable, no allocs).
// ---------------------------------------------------------------------------
extern "C" void kernel_launch(void* const* d_in, const int* in_sizes, int n_in,
                              void* d_out, int out_size) {
    const float* x = (const float*)d_in[0];
    const int n = in_sizes[0];

    k_init<<<(NBINS + 255) / 256, 256>>>();
    k_absmax<<<1184, 256>>>(x, n);
    k_hist<<<1184, 256>>>(x, n);
    k_deperm<<<(NBINS + 255) / 256, 256>>>();
    dim3 sg(NUM_T, NCHUNK);
    k_scores<<<sg, 256>>>();
    k_argmin<<<1, 32>>>((float*)d_out);
}

// round 6
// speedup vs baseline: 1.6774x; 1.6774x over previous
#include <cuda_runtime.h>
#include <math.h>
#include <stdint.h>

// ---------------------------------------------------------------------------
// MSEObserver: 100-candidate symmetric-threshold grid search, Lp loss p=2.4.
// R6: revert to R4 structure (R5's direct-32K experiment proved per-address
// atomic serialization is first-order: hot-bin counts must stay low). Single
// controlled change: histogram resolution 256K -> 1M bins (hottest bin ~110
// counts instead of ~435), pushing per-address serialization into the noise.
// Collapse 1M -> 32K via the perm gather; scoring path identical to R4.
// ---------------------------------------------------------------------------

#define NBINS_H (1 << 20)                  // 1M histogram bins (4 MB, L2-res)
#define NBINS_S (1 << 15)                  // 32768 scoring bins
#define COLLAPSE (NBINS_H / NBINS_S)       // 32
#define NUM_T 100
#define NCHUNK 8
#define BINS_PER_CHUNK (NBINS_S / NCHUNK)  // 4096

#define PERM_MULT 0x9E3779B1u              // odd -> bijective mod 2^20
#define PERM_MASK (NBINS_H - 1)
#define MAGIC 12582912.0f                  // 2^23 + 2^22
#define BIN_OFF 2.0f                       // low-side safety offset
#define BIN_SPAN ((float)(NBINS_H - 8))    // top-side safety margin

__device__ unsigned int g_absmax_bits;     // max|x| >= 0 -> raw-bit atomicMax ok
__device__ unsigned int g_hist[NBINS_H];   // permuted layout
__device__ unsigned int g_hist_s[NBINS_S]; // collapsed scoring histogram
__device__ double       g_partial[NUM_T][NCHUNK];

// ---------------------------------------------------------------------------
// K0: zero g_hist + absmax (g_hist_s / g_partial are fully overwritten each
// replay by k_collapse / k_scores -> deterministic without reset).
// ---------------------------------------------------------------------------
__global__ void k_init() {
    int idx = blockIdx.x * blockDim.x + threadIdx.x;
    int i4 = idx * 4;
    if (i4 < NBINS_H) *(uint4*)&g_hist[i4] = make_uint4(0u, 0u, 0u, 0u);
    if (idx == 0) g_absmax_bits = 0u;
}

// ---------------------------------------------------------------------------
// K1: absmax = max(|x|). One FMNMX(|.|)/elem; DRAM-roofline pass (~17 us).
// ---------------------------------------------------------------------------
__global__ void __launch_bounds__(256) k_absmax(const float* __restrict__ x, int n) {
    const int n4 = n >> 2;
    const float4* __restrict__ x4 = (const float4*)x;

    float m0 = 0.0f, m1 = 0.0f;
    for (int i = blockIdx.x * blockDim.x + threadIdx.x; i < n4;
         i += gridDim.x * blockDim.x) {
        float4 v = x4[i];
        m0 = fmaxf(m0, fmaxf(fabsf(v.x), fabsf(v.y)));
        m1 = fmaxf(m1, fmaxf(fabsf(v.z), fabsf(v.w)));
    }
    if (blockIdx.x == 0) {                       // tail
        int t = n4 * 4 + threadIdx.x;
        if (t < n) m0 = fmaxf(m0, fabsf(x[t]));
    }
    float m = fmaxf(m0, m1);

    for (int o = 16; o > 0; o >>= 1)
        m = fmaxf(m, __shfl_xor_sync(0xffffffffu, m, o));
    __shared__ float sm[8];
    int wid = threadIdx.x >> 5, lid = threadIdx.x & 31;
    if (lid == 0) sm[wid] = m;
    __syncthreads();
    if (wid == 0) {
        m = (lid < 8) ? sm[lid] : 0.0f;
        for (int o = 4; o > 0; o >>= 1)
            m = fmaxf(m, __shfl_xor_sync(0xffffffffu, m, o));
        if (lid == 0) atomicMax(&g_absmax_bits, __float_as_uint(m));
    }
}

// ---------------------------------------------------------------------------
// K2: hash-permuted 1M-bin histogram over [-xr, xr].
// bin = round((v+xr)*invw) + BIN_OFF via ONE fused FFMA + magic number;
// invw margined so 2 <= bin <= NBINS_H-6 structurally (no clamps).
// Loop shape identical to R4 (one float4 / iter) — the known-good config.
// ---------------------------------------------------------------------------
__global__ void __launch_bounds__(256) k_hist(const float* __restrict__ x, int n) {
    const float xr   = __uint_as_float(g_absmax_bits);
    const float invw = BIN_SPAN / (2.0f * xr);
    const float C    = xr * invw + (MAGIC + BIN_OFF);   // folds shift+off+magic

    const int n4 = n >> 2;
    const float4* __restrict__ x4 = (const float4*)x;

    for (int i = blockIdx.x * blockDim.x + threadIdx.x; i < n4;
         i += gridDim.x * blockDim.x) {
        float4 v = x4[i];
        float vv[4] = {v.x, v.y, v.z, v.w};
        #pragma unroll
        for (int k = 0; k < 4; k++) {
            float f = fmaf(vv[k], invw, C);               // t + magic (rn)
            unsigned int b = __float_as_uint(f) & 0x3FFFFFu;  // round(t)+OFF
            unsigned int p = (b * PERM_MULT) & PERM_MASK;
            atomicAdd(&g_hist[p], 1u);
        }
    }
    if (blockIdx.x == 0) {                                // tail
        int t = n4 * 4 + threadIdx.x;
        if (t < n) {
            float f = fmaf(x[t], invw, C);
            unsigned int b = __float_as_uint(f) & 0x3FFFFFu;
            unsigned int p = (b * PERM_MULT) & PERM_MASK;
            atomicAdd(&g_hist[p], 1u);
        }
    }
}

// ---------------------------------------------------------------------------
// K2b: collapse 1M (permuted) bins -> 32K scoring bins. Scoring bin s sums
// logical hist bins [32s, 32s+32) gathered through the permutation.
// ---------------------------------------------------------------------------
__global__ void __launch_bounds__(256) k_collapse() {
    int s = blockIdx.x * blockDim.x + threadIdx.x;
    if (s < NBINS_S) {
        unsigned int base = (unsigned int)s * COLLAPSE;
        unsigned int acc = 0u;
        #pragma unroll
        for (unsigned int j = 0; j < COLLAPSE; j++) {
            unsigned int p = ((base + j) * PERM_MULT) & PERM_MASK;
            acc += g_hist[p];
        }
        g_hist_s[s] = acc;
    }
}

// ---------------------------------------------------------------------------
// K3: grid (NUM_T, NCHUNK). Score candidate i+1 over a chunk of scoring bins.
// Logical hist bin h: center value = (h - OFF)*wH - xr. Scoring bin s covers
// hist bins [32s, 32s+32) -> center c = (32s + 15.5 - OFF)*wH - xr.
// fp32 inner loop + Kahan; double block reduce; deterministic single store.
// ---------------------------------------------------------------------------
__global__ void __launch_bounds__(256) k_scores() {
    const int i     = blockIdx.x + 1;
    const int chunk = blockIdx.y;

    const float xr   = __uint_as_float(g_absmax_bits);
    const float invw = BIN_SPAN / (2.0f * xr);
    const float wH   = 1.0f / invw;

    const float thres = xr / 100.0f * (float)i;          // match ref fp32 order
    const float scale = fmaxf(thres / 127.5f, 1e-8f);
    const float inv_scale = 1.0f / scale;

    const float c0 = (15.5f - BIN_OFF) * wH - xr;        // c = 32s*wH + c0
    const float w32 = (float)COLLAPSE * wH;

    float acc = 0.0f, comp = 0.0f;                        // Kahan
    const int b_end = (chunk + 1) * BINS_PER_CHUNK;
    for (int b = chunk * BINS_PER_CHUNK + threadIdx.x; b < b_end; b += 256) {
        unsigned int cnt = g_hist_s[b];
        if (cnt == 0u) continue;
        float c = fmaf((float)b, w32, c0);                // bin-center value
        float t = c * inv_scale;
        float r = rintf(t);                               // round half-even
        r = fminf(fmaxf(r, -128.0f), 127.0f);             // clip
        float e = fabsf(fmaf(-r, scale, c));              // |c - r*scale|
        float p = exp2f(2.4f * __log2f(e));               // e^2.4 (e=0 -> 0)
        float term = (float)cnt * p;
        float y = term - comp;
        float s = acc + y;
        comp = (s - acc) - y;
        acc = s;
    }

    __shared__ double sacc[256];
    sacc[threadIdx.x] = (double)acc;
    __syncthreads();
    for (int s = 128; s > 0; s >>= 1) {
        if (threadIdx.x < s) sacc[threadIdx.x] += sacc[threadIdx.x + s];
        __syncthreads();
    }
    if (threadIdx.x == 0) g_partial[blockIdx.x][chunk] = sacc[0];
}

// ---------------------------------------------------------------------------
// K4: fixed-order chunk sums, argmin (strict <, ascending i) -> output.
// ---------------------------------------------------------------------------
__global__ void k_argmin(float* __restrict__ out) {
    if (threadIdx.x == 0 && blockIdx.x == 0) {
        const float xr = __uint_as_float(g_absmax_bits);

        double best = 1e300;
        int bi = 1;
        #pragma unroll 1
        for (int i = 1; i <= NUM_T; i++) {
            double s = 0.0;
            #pragma unroll
            for (int c = 0; c < NCHUNK; c++) s += g_partial[i - 1][c];
            if (s < best) { best = s; bi = i; }
        }
        float thres = xr / 100.0f * (float)bi;
        out[0] = -thres;
        out[1] =  thres;
    }
}

// ---------------------------------------------------------------------------
// Launch: 6 kernels on the default stream (graph-capturable, no allocs).
// ---------------------------------------------------------------------------
extern "C" void kernel_launch(void* const* d_in, const int* in_sizes, int n_in,
                              void* d_out, int out_size) {
    const float* x = (const float*)d_in[0];
    const int n = in_sizes[0];

    k_init<<<(NBINS_H / 4 + 255) / 256, 256>>>();
    k_absmax<<<1184, 256>>>(x, n);
    k_hist<<<1184, 256>>>(x, n);
    k_collapse<<<(NBINS_S + 255) / 256, 256>>>();
    dim3 sg(NUM_T, NCHUNK);
    k_scores<<<sg, 256>>>();
    k_argmin<<<1, 32>>>((float*)d_out);
}